// round 14
// baseline (speedup 1.0000x reference)
#include <cuda_runtime.h>
#include <cuda_bf16.h>
#include <cstdint>
#include <math.h>

#define D 128
#define NU_MAX 100000
#define NI_MAX 50000
#define E_MAX  500000

// ---------------- scratch (device globals; no allocation allowed) ----------------
__device__ float4 g_agg_user4[(size_t)NU_MAX * D / 4];
__device__ float4 g_agg_item4[(size_t)NI_MAX * D / 4];
__device__ float  g_deg_user[NU_MAX];
__device__ float  g_deg_item[NI_MAX];
// pre-split, pre-swizzled bf16 weights: tiles m = {W1hi, W1lo, W2hi, W2lo} x {half0, half1}
__device__ unsigned char g_wt[4 * 2 * 16384];
// bucket-CSR build scratch: node index space = [0,NI) items, [NI, NI+NU) users
__device__ int   g_cnt[NU_MAX + NI_MAX];
__device__ int   g_base[NU_MAX + NI_MAX];
__device__ int   g_wr[NU_MAX + NI_MAX];
__device__ int   g_cursor[2];
__device__ uint2 g_epack_u2i[E_MAX];   // (src_user, norm_bits), grouped by dst item
__device__ uint2 g_epack_i2u[E_MAX];   // (src_item, norm_bits), grouped by dst user

// ---------------- helpers ----------------
__device__ __forceinline__ uint32_t smem_u32(const void* p) {
    uint32_t a;
    asm("{ .reg .u64 t; cvta.to.shared.u64 t, %1; cvt.u32.u64 %0, t; }" : "=r"(a) : "l"(p));
    return a;
}
__device__ __forceinline__ void ldmx4(uint32_t* r, uint32_t addr) {
    asm volatile("ldmatrix.sync.aligned.m8n8.x4.shared.b16 {%0,%1,%2,%3}, [%4];"
                 : "=r"(r[0]), "=r"(r[1]), "=r"(r[2]), "=r"(r[3]) : "r"(addr));
}
__device__ __forceinline__ void mma16816(float* c, const uint32_t* a, uint32_t b0, uint32_t b1) {
    asm volatile("mma.sync.aligned.m16n8k16.row.col.f32.bf16.bf16.f32 "
                 "{%0,%1,%2,%3}, {%4,%5,%6,%7}, {%8,%9}, {%0,%1,%2,%3};"
                 : "+f"(c[0]), "+f"(c[1]), "+f"(c[2]), "+f"(c[3])
                 : "r"(a[0]), "r"(a[1]), "r"(a[2]), "r"(a[3]), "r"(b0), "r"(b1));
}
__device__ __forceinline__ void pack_hl(const float* v, uint4* hi, uint4* lo) {
    uint32_t h[4], l[4];
    #pragma unroll
    for (int i = 0; i < 4; ++i) {
        float2 p = make_float2(v[2 * i], v[2 * i + 1]);
        __nv_bfloat162 hb = __float22bfloat162_rn(p);
        float2 r = make_float2(p.x - __bfloat162float(hb.x),
                               p.y - __bfloat162float(hb.y));
        __nv_bfloat162 lb = __float22bfloat162_rn(r);
        h[i] = *(uint32_t*)&hb;
        l[i] = *(uint32_t*)&lb;
    }
    *hi = make_uint4(h[0], h[1], h[2], h[3]);
    *lo = make_uint4(l[0], l[1], l[2], l[3]);
}
#define CP_ASYNC16(saddr, gptr) \
    asm volatile("cp.async.cg.shared.global [%0], [%1], 16;" :: "r"(saddr), "l"(gptr) : "memory")
#define CP_COMMIT() asm volatile("cp.async.commit_group;" ::: "memory")
#define CP_WAIT0()  asm volatile("cp.async.wait_group 0;" ::: "memory")

// ---------------- init: zero counters + weight split/swizzle (merged) ----------------
__global__ void init_kernel(const float* __restrict__ W1, const float* __restrict__ W2,
                            int total_nodes) {
    int i = blockIdx.x * blockDim.x + threadIdx.x;
    if (i < 2) g_cursor[i] = 0;
    if (i < total_nodes) g_cnt[i] = 0;
    if (i < 2 * D * D) {
        int w = i >> 14;           // 0 = W1, 1 = W2
        int k = (i >> 7) & 127;
        int n = i & 127;
        float v = __ldg((w ? W2 : W1) + k * D + n);
        __nv_bfloat16 hb = __float2bfloat16(v);
        __nv_bfloat16 lb = __float2bfloat16(v - __bfloat162float(hb));
        int h = n >> 6, np = n & 63;
        // tile layout: [64 n-rows][128 k] bf16, 256B rows... stored as n'*256 + swizzled chunk
        uint32_t off = (uint32_t)(np * 256 + (((k >> 3) ^ (np & 7)) * 16) + (k & 7) * 2);
        *(__nv_bfloat16*)(g_wt + ((2 * w + 0) * 2 + h) * 16384 + off) = hb;
        *(__nv_bfloat16*)(g_wt + ((2 * w + 1) * 2 + h) * 16384 + off) = lb;
    }
}

// ---------------- build phase ----------------
__global__ void count_kernel(const int* __restrict__ dst_u2i,
                             const int* __restrict__ dst_i2u, int E, int NI) {
    int i = blockIdx.x * blockDim.x + threadIdx.x;
    if (i < E) {
        atomicAdd(&g_cnt[__ldg(dst_u2i + i)], 1);
    } else if (i < 2 * E) {
        atomicAdd(&g_cnt[NI + __ldg(dst_i2u + (i - E))], 1);
    }
}

template <int DIR>
__global__ void base_scan_kernel(int n, int node0) {
    int i = blockIdx.x * 256 + threadIdx.x;
    int lane = threadIdx.x & 31;
    int w = threadIdx.x >> 5;
    int c = (i < n) ? g_cnt[node0 + i] : 0;
    int x = c;
    #pragma unroll
    for (int o = 1; o < 32; o <<= 1) {
        int t = __shfl_up_sync(0xffffffffu, x, o);
        if (lane >= o) x += t;
    }
    __shared__ int wsum[8];
    __shared__ int bbase;
    if (lane == 31) wsum[w] = x;
    __syncthreads();
    int wpre = 0;
    #pragma unroll
    for (int j = 0; j < 8; ++j) wpre += (j < w) ? wsum[j] : 0;
    int incl = x + wpre;
    if (threadIdx.x == 255) bbase = atomicAdd(&g_cursor[DIR], incl);
    __syncthreads();
    if (i < n) {
        int b = bbase + incl - c;
        g_base[node0 + i] = b;
        g_wr[node0 + i] = b;
    }
}

__global__ void fill_kernel(const int* __restrict__ src_u2i,
                            const int* __restrict__ dst_u2i,
                            const float* __restrict__ norm_u2i,
                            const int* __restrict__ src_i2u,
                            const int* __restrict__ dst_i2u,
                            const float* __restrict__ norm_i2u,
                            int E, int NI) {
    int i = blockIdx.x * blockDim.x + threadIdx.x;
    if (i < E) {
        int d = __ldg(dst_u2i + i);
        int p = atomicAdd(&g_wr[d], 1);
        if (p < E_MAX)
            g_epack_u2i[p] = make_uint2((uint32_t)__ldg(src_u2i + i),
                                        __float_as_uint(__ldg(norm_u2i + i)));
    } else if (i < 2 * E) {
        int j = i - E;
        int d = __ldg(dst_i2u + j);
        int p = atomicAdd(&g_wr[NI + d], 1);
        if (p < E_MAX)
            g_epack_i2u[p] = make_uint2((uint32_t)__ldg(src_i2u + j),
                                        __float_as_uint(__ldg(norm_i2u + j)));
    }
}

// ---------------- gather: one warp per dst node, no atomics, no pre-zero ----------------
__global__ void gather_kernel(const float* __restrict__ feat_user,
                              const float* __restrict__ feat_item,
                              int NU, int NI) {
    int gw = (blockIdx.x * blockDim.x + threadIdx.x) >> 5;
    int lane = threadIdx.x & 31;
    int total = NI + NU;
    if (gw >= total) return;

    const bool is_item = gw < NI;
    const int node = is_item ? gw : gw - NI;
    const float* fs = is_item ? feat_user : feat_item;
    const uint2* ep = is_item ? g_epack_u2i : g_epack_i2u;
    float4* agg = is_item ? (g_agg_item4 + (size_t)node * 32)
                          : (g_agg_user4 + (size_t)node * 32);
    float* degp = is_item ? (g_deg_item + node) : (g_deg_user + node);

    int e  = __ldg(g_base + gw);
    int e1 = e + __ldg(g_cnt + gw);

    float4 acc = make_float4(0.f, 0.f, 0.f, 0.f);
    float dg = 0.f;
    uint2 pk;
    float4 f;
    if (e < e1) {
        pk = __ldg(ep + e);
        f = __ldg(((const float4*)(fs + (size_t)pk.x * D)) + lane);
    }
    while (e < e1) {
        float w = __uint_as_float(pk.y);
        float4 cf = f;
        ++e;
        if (e < e1) {
            pk = __ldg(ep + e);
            f = __ldg(((const float4*)(fs + (size_t)pk.x * D)) + lane);
        }
        acc.x += w * cf.x;
        acc.y += w * cf.y;
        acc.z += w * cf.z;
        acc.w += w * cf.w;
        dg += w;
    }
    agg[lane] = acc;
    if (lane == 0) *degp = dg;
}

// ---------------- mma.sync fused dual-GEMM + bias + LeakyReLU + row L2-normalize ----------------
// 512 threads / 16 warps, warp tile 16 rows x 32 cols per half.
// smem: 4 A-operand tiles (Ahi, Alo, Bhi, Blo) [128 rows][256B] = 128KB, then 4 W tiles 16KB each.
// W tiles pipelined via cp.async: half0 prefetched behind A staging; half1 behind compute.
#define SM_W_OFF 131072
#define SM_TOTAL (131072 + 65536)

__global__ __launch_bounds__(512, 1)
void gemm_mma_kernel(const float* __restrict__ feat_user,
                     const float* __restrict__ feat_item,
                     const float* __restrict__ b1v,
                     const float* __restrict__ b2v,
                     float* __restrict__ out,
                     int NU, int NI, int ublocks) {
    extern __shared__ char smem[];
    const uint32_t sbase = smem_u32(smem);
    const int tid = threadIdx.x;
    const int wid = tid >> 5;
    const int lane = tid & 31;

    const bool is_user = (int)blockIdx.x < ublocks;
    const int bx = is_user ? blockIdx.x : blockIdx.x - ublocks;
    const int Nrows = is_user ? NU : NI;
    const int row0 = bx * 128;
    const float* feat = is_user ? feat_user : feat_item;
    const float* agg  = is_user ? (const float*)g_agg_user4 : (const float*)g_agg_item4;
    const float* deg  = is_user ? g_deg_user : g_deg_item;
    float* outp = is_user ? out : out + (size_t)NU * D;

    // ---- prefetch W half-0 (4 tiles) via cp.async, overlapped with A staging ----
    #pragma unroll
    for (int m = 0; m < 4; ++m)
        for (int t = tid; t < 1024; t += 512)
            CP_ASYNC16(sbase + SM_W_OFF + m * 16384 + t * 16,
                       (const void*)(g_wt + (m * 2 + 0) * 16384 + t * 16));
    CP_COMMIT();

    // ---- stage A-operand tiles: thread t -> row t>>2, k-quarter t&3 (4 chunks of 8 k) ----
    {
        int r = tid >> 2, kq = tid & 3;
        int grow = row0 + r;
        bool valid = grow < Nrows;
        const float4* fp = (const float4*)(feat + (size_t)grow * D);
        const float4* ap = (const float4*)(agg  + (size_t)grow * D);
        const float4 z = make_float4(0.f, 0.f, 0.f, 0.f);
        uint32_t rbase = (uint32_t)(r * 256);
        int rs = r & 7;
        #pragma unroll
        for (int j = 0; j < 4; ++j) {
            int c = kq * 4 + j;
            float4 f0 = valid ? __ldg(fp + 2 * c)     : z;
            float4 f1 = valid ? __ldg(fp + 2 * c + 1) : z;
            float4 a0 = valid ? __ldg(ap + 2 * c)     : z;
            float4 a1 = valid ? __ldg(ap + 2 * c + 1) : z;
            float Av[8] = {f0.x + a0.x, f0.y + a0.y, f0.z + a0.z, f0.w + a0.w,
                           f1.x + a1.x, f1.y + a1.y, f1.z + a1.z, f1.w + a1.w};
            float Bv[8] = {f0.x * a0.x, f0.y * a0.y, f0.z * a0.z, f0.w * a0.w,
                           f1.x * a1.x, f1.y * a1.y, f1.z * a1.z, f1.w * a1.w};
            uint32_t off = rbase + (uint32_t)((c ^ rs) * 16);
            uint4 hi, lo;
            pack_hl(Av, &hi, &lo);
            *(uint4*)(smem + 0 * 32768 + off) = hi;
            *(uint4*)(smem + 1 * 32768 + off) = lo;
            pack_hl(Bv, &hi, &lo);
            *(uint4*)(smem + 2 * 32768 + off) = hi;
            *(uint4*)(smem + 3 * 32768 + off) = lo;
        }
    }
    CP_WAIT0();
    __syncthreads();

    const int rg = wid & 7;      // 8 row groups of 16 rows
    const int cg = wid >> 3;     // 2 col groups of 32 cols (within current 64-col half)
    const int lrow = lane & 15;
    const int lkh = lane >> 4;
    const int lswz = lrow & 7;

    float acc[2][4][4];          // [h][nb][c]
    #pragma unroll
    for (int h = 0; h < 2; ++h)
        #pragma unroll
        for (int nb = 0; nb < 4; ++nb)
            #pragma unroll
            for (int e = 0; e < 4; ++e) acc[h][nb][e] = 0.f;

    const int aidx[6] = {0, 0, 1, 2, 2, 3};   // Ahi Ahi Alo Bhi Bhi Blo
    const int widx[6] = {0, 1, 0, 2, 3, 2};   // W1hi W1lo W1hi W2hi W2lo W2hi

    const uint32_t rowA = (uint32_t)((rg * 16 + lrow) * 256);
    const uint32_t rowB0 = (uint32_t)((cg * 32 + lrow) * 256);
    const uint32_t rowB1 = rowB0 + 16 * 256;

    auto run_passes = [&](int h, int p0, int p1) {
        for (int p = p0; p <= p1; ++p) {
            const uint32_t abase = sbase + (uint32_t)(aidx[p] * 32768);
            const uint32_t wbase = sbase + SM_W_OFF + (uint32_t)(widx[p] * 16384);
            #pragma unroll
            for (int ks = 0; ks < 8; ++ks) {
                uint32_t coff = (uint32_t)(((ks * 2 + lkh) ^ lswz) * 16);
                uint32_t ar[4], b0r[4], b1r[4];
                ldmx4(ar, abase + rowA + coff);
                ldmx4(b0r, wbase + rowB0 + coff);
                ldmx4(b1r, wbase + rowB1 + coff);
                mma16816(acc[h][0], ar, b0r[0], b0r[2]);
                mma16816(acc[h][1], ar, b0r[1], b0r[3]);
                mma16816(acc[h][2], ar, b1r[0], b1r[2]);
                mma16816(acc[h][3], ar, b1r[1], b1r[3]);
            }
        }
    };

    // half 0, W1 passes (slots 0,1)
    run_passes(0, 0, 2);
    __syncthreads();                       // everyone done with W1 slots
    // prefetch half-1 W1 tiles into slots 0,1 while half-0 W2 passes run
    #pragma unroll
    for (int m = 0; m < 2; ++m)
        for (int t = tid; t < 1024; t += 512)
            CP_ASYNC16(sbase + SM_W_OFF + m * 16384 + t * 16,
                       (const void*)(g_wt + (m * 2 + 1) * 16384 + t * 16));
    CP_COMMIT();
    run_passes(0, 3, 5);                   // uses slots 2,3
    CP_WAIT0();
    __syncthreads();                       // W1' landed; everyone done with W2 slots
    // prefetch half-1 W2 tiles into slots 2,3 while half-1 W1 passes run
    #pragma unroll
    for (int m = 2; m < 4; ++m)
        for (int t = tid; t < 1024; t += 512)
            CP_ASYNC16(sbase + SM_W_OFF + m * 16384 + t * 16,
                       (const void*)(g_wt + (m * 2 + 1) * 16384 + t * 16));
    CP_COMMIT();
    run_passes(1, 0, 2);                   // uses slots 0,1 (half-1 W1)
    CP_WAIT0();
    __syncthreads();
    run_passes(1, 3, 5);                   // uses slots 2,3 (half-1 W2)
    __syncthreads();                       // before smem reuse in epilogue

    // ---- epilogue: bias, LeakyReLU(0.2), row L2 normalize, store ----
    const int rl = lane >> 2;
    float dg2[2], ss2[2];
    #pragma unroll
    for (int rh = 0; rh < 2; ++rh) {
        int grow = row0 + rg * 16 + rh * 8 + rl;
        dg2[rh] = (grow < Nrows) ? __ldg(deg + grow) : 0.f;
        ss2[rh] = 0.f;
    }

    #pragma unroll
    for (int h = 0; h < 2; ++h)
        #pragma unroll
        for (int nb = 0; nb < 4; ++nb) {
            int col = h * 64 + cg * 32 + nb * 8 + (lane & 3) * 2;
            float2 bb1 = __ldg((const float2*)(b1v + col));
            float2 bb2 = __ldg((const float2*)(b2v + col));
            #pragma unroll
            for (int rh = 0; rh < 2; ++rh) {
                float d = dg2[rh];
                float* c = acc[h][nb] + rh * 2;
                float h0 = c[0] + (1.f + d) * bb1.x + d * bb2.x;
                float h1 = c[1] + (1.f + d) * bb1.y + d * bb2.y;
                h0 = (h0 > 0.f) ? h0 : 0.2f * h0;
                h1 = (h1 > 0.f) ? h1 : 0.2f * h1;
                c[0] = h0; c[1] = h1;
                ss2[rh] += h0 * h0 + h1 * h1;
            }
        }
    #pragma unroll
    for (int off = 1; off <= 2; off <<= 1)
        #pragma unroll
        for (int rh = 0; rh < 2; ++rh)
            ss2[rh] += __shfl_xor_sync(0xffffffffu, ss2[rh], off);

    float* part = (float*)smem;   // [2 cg][128 rows]
    if ((lane & 3) == 0) {
        #pragma unroll
        for (int rh = 0; rh < 2; ++rh)
            part[cg * 128 + rg * 16 + rh * 8 + rl] = ss2[rh];
    }
    __syncthreads();

    #pragma unroll
    for (int rh = 0; rh < 2; ++rh) {
        int lrow128 = rg * 16 + rh * 8 + rl;
        int grow = row0 + lrow128;
        float tot = ss2[rh] + part[(1 ^ cg) * 128 + lrow128];
        float inv = 1.f / fmaxf(sqrtf(tot), 1e-12f);
        if (grow < Nrows) {
            #pragma unroll
            for (int h = 0; h < 2; ++h)
                #pragma unroll
                for (int nb = 0; nb < 4; ++nb) {
                    int col = h * 64 + cg * 32 + nb * 8 + (lane & 3) * 2;
                    float* c = acc[h][nb] + rh * 2;
                    *(float2*)(outp + (size_t)grow * D + col) =
                        make_float2(c[0] * inv, c[1] * inv);
                }
        }
    }
}

// ---------------- launch ----------------
extern "C" void kernel_launch(void* const* d_in, const int* in_sizes, int n_in,
                              void* d_out, int out_size) {
    const float* feat_user = (const float*)d_in[0];
    const float* feat_item = (const float*)d_in[1];
    const float* W1        = (const float*)d_in[2];
    const float* b1        = (const float*)d_in[3];
    const float* W2        = (const float*)d_in[4];
    const float* b2        = (const float*)d_in[5];
    const float* norm_u2i  = (const float*)d_in[6];
    const float* norm_i2u  = (const float*)d_in[7];
    const int*   e_ui_src  = (const int*)d_in[8];
    const int*   e_ui_dst  = (const int*)d_in[9];
    const int*   e_iu_src  = (const int*)d_in[10];
    const int*   e_iu_dst  = (const int*)d_in[11];
    float* out = (float*)d_out;

    const int NU = in_sizes[0] / D;
    const int NI = in_sizes[1] / D;
    const int E  = in_sizes[8];
    const int total_nodes = NU + NI;

    cudaFuncSetAttribute((const void*)gemm_mma_kernel,
                         cudaFuncAttributeMaxDynamicSharedMemorySize, SM_TOTAL);

    int init_n = total_nodes > 2 * D * D ? total_nodes : 2 * D * D;
    init_kernel<<<(init_n + 255) / 256, 256>>>(W1, W2, total_nodes);
    count_kernel<<<(2 * E + 255) / 256, 256>>>(e_ui_dst, e_iu_dst, E, NI);
    base_scan_kernel<0><<<(NI + 255) / 256, 256>>>(NI, 0);     // items
    base_scan_kernel<1><<<(NU + 255) / 256, 256>>>(NU, NI);    // users
    fill_kernel<<<(2 * E + 255) / 256, 256>>>(e_ui_src, e_ui_dst, norm_u2i,
                                              e_iu_src, e_iu_dst, norm_i2u, E, NI);
    gather_kernel<<<(total_nodes + 7) / 8, 256>>>(feat_user, feat_item, NU, NI);

    const int ublocks = (NU + 127) / 128;
    const int iblocks = (NI + 127) / 128;
    gemm_mma_kernel<<<ublocks + iblocks, 512, SM_TOTAL>>>(
        feat_user, feat_item, b1, b2, out, NU, NI, ublocks);
}

// round 15
// speedup vs baseline: 1.0803x; 1.0803x over previous
#include <cuda_runtime.h>
#include <cuda_bf16.h>
#include <cstdint>
#include <math.h>

#define D 128
#define NU_MAX 100000
#define NI_MAX 50000
#define E_MAX  500000

// ---------------- scratch (device globals; no allocation allowed) ----------------
__device__ float4 g_agg_user4[(size_t)NU_MAX * D / 4];
__device__ float4 g_agg_item4[(size_t)NI_MAX * D / 4];
__device__ float  g_deg_user[NU_MAX];
__device__ float  g_deg_item[NI_MAX];
// pre-split, pre-swizzled bf16 weights: tiles m = {W1hi, W1lo, W2hi, W2lo},
// each [128 n-rows][128 k] bf16, row = 256B, chunk (16B) swizzled by (n&7). 32KB/tile.
// n-halves are contiguous 16KB slabs (n*256 layout).
__device__ unsigned char g_wt[4 * 32768];
// bucket-CSR build scratch: node index space = [0,NI) items, [NI, NI+NU) users
__device__ int   g_cnt[NU_MAX + NI_MAX];
__device__ int   g_base[NU_MAX + NI_MAX];
__device__ int   g_wr[NU_MAX + NI_MAX];
__device__ int   g_cursor[2];
__device__ uint2 g_epack_u2i[E_MAX];   // (src_user, norm_bits), grouped by dst item
__device__ uint2 g_epack_i2u[E_MAX];   // (src_item, norm_bits), grouped by dst user

// ---------------- helpers ----------------
__device__ __forceinline__ uint32_t smem_u32(const void* p) {
    uint32_t a;
    asm("{ .reg .u64 t; cvta.to.shared.u64 t, %1; cvt.u32.u64 %0, t; }" : "=r"(a) : "l"(p));
    return a;
}
__device__ __forceinline__ void ldmx4(uint32_t* r, uint32_t addr) {
    asm volatile("ldmatrix.sync.aligned.m8n8.x4.shared.b16 {%0,%1,%2,%3}, [%4];"
                 : "=r"(r[0]), "=r"(r[1]), "=r"(r[2]), "=r"(r[3]) : "r"(addr));
}
__device__ __forceinline__ void mma16816(float* c, const uint32_t* a, uint32_t b0, uint32_t b1) {
    asm volatile("mma.sync.aligned.m16n8k16.row.col.f32.bf16.bf16.f32 "
                 "{%0,%1,%2,%3}, {%4,%5,%6,%7}, {%8,%9}, {%0,%1,%2,%3};"
                 : "+f"(c[0]), "+f"(c[1]), "+f"(c[2]), "+f"(c[3])
                 : "r"(a[0]), "r"(a[1]), "r"(a[2]), "r"(a[3]), "r"(b0), "r"(b1));
}
__device__ __forceinline__ void pack_hl(const float* v, uint4* hi, uint4* lo) {
    uint32_t h[4], l[4];
    #pragma unroll
    for (int i = 0; i < 4; ++i) {
        float2 p = make_float2(v[2 * i], v[2 * i + 1]);
        __nv_bfloat162 hb = __float22bfloat162_rn(p);
        float2 r = make_float2(p.x - __bfloat162float(hb.x),
                               p.y - __bfloat162float(hb.y));
        __nv_bfloat162 lb = __float22bfloat162_rn(r);
        h[i] = *(uint32_t*)&hb;
        l[i] = *(uint32_t*)&lb;
    }
    *hi = make_uint4(h[0], h[1], h[2], h[3]);
    *lo = make_uint4(l[0], l[1], l[2], l[3]);
}
#define CP_ASYNC16(saddr, gptr) \
    asm volatile("cp.async.cg.shared.global [%0], [%1], 16;" :: "r"(saddr), "l"(gptr) : "memory")
#define CP_COMMIT() asm volatile("cp.async.commit_group;" ::: "memory")
#define CP_WAIT0()  asm volatile("cp.async.wait_group 0;" ::: "memory")

// ---------------- init: zero counters + weight split/swizzle (merged) ----------------
__global__ void init_kernel(const float* __restrict__ W1, const float* __restrict__ W2,
                            int total_nodes) {
    int i = blockIdx.x * blockDim.x + threadIdx.x;
    if (i < 2) g_cursor[i] = 0;
    if (i < total_nodes) g_cnt[i] = 0;
    if (i < 2 * D * D) {
        int w = i >> 14;           // 0 = W1, 1 = W2
        int k = (i >> 7) & 127;
        int n = i & 127;
        float v = __ldg((w ? W2 : W1) + k * D + n);
        __nv_bfloat16 hb = __float2bfloat16(v);
        __nv_bfloat16 lb = __float2bfloat16(v - __bfloat162float(hb));
        uint32_t off = (uint32_t)(n * 256 + (((k >> 3) ^ (n & 7)) * 16) + (k & 7) * 2);
        *(__nv_bfloat16*)(g_wt + (2 * w + 0) * 32768 + off) = hb;
        *(__nv_bfloat16*)(g_wt + (2 * w + 1) * 32768 + off) = lb;
    }
}

// ---------------- build phase ----------------
__global__ void count_kernel(const int* __restrict__ dst_u2i,
                             const int* __restrict__ dst_i2u, int E, int NI) {
    int i = blockIdx.x * blockDim.x + threadIdx.x;
    if (i < E) {
        atomicAdd(&g_cnt[__ldg(dst_u2i + i)], 1);
    } else if (i < 2 * E) {
        atomicAdd(&g_cnt[NI + __ldg(dst_i2u + (i - E))], 1);
    }
}

template <int DIR>
__global__ void base_scan_kernel(int n, int node0) {
    int i = blockIdx.x * 256 + threadIdx.x;
    int lane = threadIdx.x & 31;
    int w = threadIdx.x >> 5;
    int c = (i < n) ? g_cnt[node0 + i] : 0;
    int x = c;
    #pragma unroll
    for (int o = 1; o < 32; o <<= 1) {
        int t = __shfl_up_sync(0xffffffffu, x, o);
        if (lane >= o) x += t;
    }
    __shared__ int wsum[8];
    __shared__ int bbase;
    if (lane == 31) wsum[w] = x;
    __syncthreads();
    int wpre = 0;
    #pragma unroll
    for (int j = 0; j < 8; ++j) wpre += (j < w) ? wsum[j] : 0;
    int incl = x + wpre;
    if (threadIdx.x == 255) bbase = atomicAdd(&g_cursor[DIR], incl);
    __syncthreads();
    if (i < n) {
        int b = bbase + incl - c;
        g_base[node0 + i] = b;
        g_wr[node0 + i] = b;
    }
}

__global__ void fill_kernel(const int* __restrict__ src_u2i,
                            const int* __restrict__ dst_u2i,
                            const float* __restrict__ norm_u2i,
                            const int* __restrict__ src_i2u,
                            const int* __restrict__ dst_i2u,
                            const float* __restrict__ norm_i2u,
                            int E, int NI) {
    int i = blockIdx.x * blockDim.x + threadIdx.x;
    if (i < E) {
        int d = __ldg(dst_u2i + i);
        int p = atomicAdd(&g_wr[d], 1);
        if (p < E_MAX)
            g_epack_u2i[p] = make_uint2((uint32_t)__ldg(src_u2i + i),
                                        __float_as_uint(__ldg(norm_u2i + i)));
    } else if (i < 2 * E) {
        int j = i - E;
        int d = __ldg(dst_i2u + j);
        int p = atomicAdd(&g_wr[NI + d], 1);
        if (p < E_MAX)
            g_epack_i2u[p] = make_uint2((uint32_t)__ldg(src_i2u + j),
                                        __float_as_uint(__ldg(norm_i2u + j)));
    }
}

// ---------------- gather: one warp per dst node, no atomics, no pre-zero ----------------
__global__ void gather_kernel(const float* __restrict__ feat_user,
                              const float* __restrict__ feat_item,
                              int NU, int NI) {
    int gw = (blockIdx.x * blockDim.x + threadIdx.x) >> 5;
    int lane = threadIdx.x & 31;
    int total = NI + NU;
    if (gw >= total) return;

    const bool is_item = gw < NI;
    const int node = is_item ? gw : gw - NI;
    const float* fs = is_item ? feat_user : feat_item;
    const uint2* ep = is_item ? g_epack_u2i : g_epack_i2u;
    float4* agg = is_item ? (g_agg_item4 + (size_t)node * 32)
                          : (g_agg_user4 + (size_t)node * 32);
    float* degp = is_item ? (g_deg_item + node) : (g_deg_user + node);

    int e  = __ldg(g_base + gw);
    int e1 = e + __ldg(g_cnt + gw);

    float4 acc = make_float4(0.f, 0.f, 0.f, 0.f);
    float dg = 0.f;
    uint2 pk;
    float4 f;
    if (e < e1) {
        pk = __ldg(ep + e);
        f = __ldg(((const float4*)(fs + (size_t)pk.x * D)) + lane);
    }
    while (e < e1) {
        float w = __uint_as_float(pk.y);
        float4 cf = f;
        ++e;
        if (e < e1) {
            pk = __ldg(ep + e);
            f = __ldg(((const float4*)(fs + (size_t)pk.x * D)) + lane);
        }
        acc.x += w * cf.x;
        acc.y += w * cf.y;
        acc.z += w * cf.z;
        acc.w += w * cf.w;
        dg += w;
    }
    agg[lane] = acc;
    if (lane == 0) *degp = dg;
}

// ---------------- mma.sync fused dual-GEMM + bias + LeakyReLU + row L2-normalize ----------------
// Round-13 proven shape: 256 threads / 8 warps, warp tile 32 rows x 16 cols,
// 4 LDSM : 8 MMA reuse ratio. Added: cp.async slot-pipelined W copies.
// smem: 4 A tiles (Ahi, Alo, Bhi, Blo) [128 rows][256B] = 128KB, then 4 W tiles 16KB each.
#define SM_W_OFF 131072
#define SM_TOTAL (131072 + 65536)

__global__ __launch_bounds__(256, 1)
void gemm_mma_kernel(const float* __restrict__ feat_user,
                     const float* __restrict__ feat_item,
                     const float* __restrict__ b1v,
                     const float* __restrict__ b2v,
                     float* __restrict__ out,
                     int NU, int NI, int ublocks) {
    extern __shared__ char smem[];
    const uint32_t sbase = smem_u32(smem);
    const int tid = threadIdx.x;
    const int wid = tid >> 5;
    const int lane = tid & 31;

    const bool is_user = (int)blockIdx.x < ublocks;
    const int bx = is_user ? blockIdx.x : blockIdx.x - ublocks;
    const int Nrows = is_user ? NU : NI;
    const int row0 = bx * 128;
    const float* feat = is_user ? feat_user : feat_item;
    const float* agg  = is_user ? (const float*)g_agg_user4 : (const float*)g_agg_item4;
    const float* deg  = is_user ? g_deg_user : g_deg_item;
    float* outp = is_user ? out : out + (size_t)NU * D;

    // ---- prefetch W half-0 (4 tiles x 16KB) via cp.async, overlapped with A staging ----
    #pragma unroll
    for (int m = 0; m < 4; ++m)
        for (int t = tid; t < 1024; t += 256)
            CP_ASYNC16(sbase + SM_W_OFF + m * 16384 + t * 16,
                       (const void*)(g_wt + m * 32768 + t * 16));
    CP_COMMIT();

    // ---- stage A-operand tiles: thread t -> row t>>1, k-half t&1 (8 chunks of 8 k) ----
    {
        int r = tid >> 1, khalf = tid & 1;
        int grow = row0 + r;
        bool valid = grow < Nrows;
        const float4* fp = (const float4*)(feat + (size_t)grow * D) + khalf * 16;
        const float4* ap = (const float4*)(agg  + (size_t)grow * D) + khalf * 16;
        const float4 z = make_float4(0.f, 0.f, 0.f, 0.f);
        uint32_t rbase = (uint32_t)(r * 256);
        int rs = r & 7;
        #pragma unroll
        for (int j = 0; j < 8; ++j) {
            float4 f0 = valid ? __ldg(fp + 2 * j)     : z;
            float4 f1 = valid ? __ldg(fp + 2 * j + 1) : z;
            float4 a0 = valid ? __ldg(ap + 2 * j)     : z;
            float4 a1 = valid ? __ldg(ap + 2 * j + 1) : z;
            float Av[8] = {f0.x + a0.x, f0.y + a0.y, f0.z + a0.z, f0.w + a0.w,
                           f1.x + a1.x, f1.y + a1.y, f1.z + a1.z, f1.w + a1.w};
            float Bv[8] = {f0.x * a0.x, f0.y * a0.y, f0.z * a0.z, f0.w * a0.w,
                           f1.x * a1.x, f1.y * a1.y, f1.z * a1.z, f1.w * a1.w};
            uint32_t off = rbase + (uint32_t)((((khalf * 8 + j) ^ rs)) * 16);
            uint4 hi, lo;
            pack_hl(Av, &hi, &lo);
            *(uint4*)(smem + 0 * 32768 + off) = hi;
            *(uint4*)(smem + 1 * 32768 + off) = lo;
            pack_hl(Bv, &hi, &lo);
            *(uint4*)(smem + 2 * 32768 + off) = hi;
            *(uint4*)(smem + 3 * 32768 + off) = lo;
        }
    }
    CP_WAIT0();
    __syncthreads();

    const int rg = wid & 3;      // 4 row groups of 32 rows
    const int cg = wid >> 2;     // 2 col groups of 32 cols (within current 64-col half)
    const int lrow = lane & 15;
    const int lkh = lane >> 4;
    const int lswz = lrow & 7;

    float acc[2][2][4][4];       // [h][mb][nb][c]
    #pragma unroll
    for (int h = 0; h < 2; ++h)
        #pragma unroll
        for (int mb = 0; mb < 2; ++mb)
            #pragma unroll
            for (int nb = 0; nb < 4; ++nb)
                #pragma unroll
                for (int e = 0; e < 4; ++e) acc[h][mb][nb][e] = 0.f;

    const int aidx[6] = {0, 0, 1, 2, 2, 3};   // Ahi Ahi Alo Bhi Bhi Blo
    const int widx[6] = {0, 1, 0, 2, 3, 2};   // W1hi W1lo W1hi W2hi W2lo W2hi

    const uint32_t rowA0 = (uint32_t)((rg * 32 + lrow) * 256);
    const uint32_t rowA1 = rowA0 + 16 * 256;
    const uint32_t rowB0 = (uint32_t)((cg * 32 + lrow) * 256);
    const uint32_t rowB1 = rowB0 + 16 * 256;

    auto run_passes = [&](int h, int p0, int p1) {
        for (int p = p0; p <= p1; ++p) {
            const uint32_t abase = sbase + (uint32_t)(aidx[p] * 32768);
            const uint32_t wbase = sbase + SM_W_OFF + (uint32_t)(widx[p] * 16384);
            #pragma unroll
            for (int ks = 0; ks < 8; ++ks) {
                uint32_t coff = (uint32_t)(((ks * 2 + lkh) ^ lswz) * 16);
                uint32_t a0r[4], a1r[4], b0r[4], b1r[4];
                ldmx4(a0r, abase + rowA0 + coff);
                ldmx4(a1r, abase + rowA1 + coff);
                ldmx4(b0r, wbase + rowB0 + coff);
                ldmx4(b1r, wbase + rowB1 + coff);
                #pragma unroll
                for (int mb = 0; mb < 2; ++mb) {
                    const uint32_t* a = mb ? a1r : a0r;
                    mma16816(acc[h][mb][0], a, b0r[0], b0r[2]);
                    mma16816(acc[h][mb][1], a, b0r[1], b0r[3]);
                    mma16816(acc[h][mb][2], a, b1r[0], b1r[2]);
                    mma16816(acc[h][mb][3], a, b1r[1], b1r[3]);
                }
            }
        }
    };

    // half 0, W1 passes (W slots 0,1)
    run_passes(0, 0, 2);
    __syncthreads();                       // all warps done with slots 0,1
    // prefetch half-1 W1 tiles into slots 0,1 behind half-0's W2 passes
    #pragma unroll
    for (int m = 0; m < 2; ++m)
        for (int t = tid; t < 1024; t += 256)
            CP_ASYNC16(sbase + SM_W_OFF + m * 16384 + t * 16,
                       (const void*)(g_wt + m * 32768 + 16384 + t * 16));
    CP_COMMIT();
    run_passes(0, 3, 5);                   // uses slots 2,3
    CP_WAIT0();
    __syncthreads();                       // W1' landed; all warps done with slots 2,3
    // prefetch half-1 W2 tiles into slots 2,3 behind half-1's W1 passes
    #pragma unroll
    for (int m = 2; m < 4; ++m)
        for (int t = tid; t < 1024; t += 256)
            CP_ASYNC16(sbase + SM_W_OFF + m * 16384 + t * 16,
                       (const void*)(g_wt + m * 32768 + 16384 + t * 16));
    CP_COMMIT();
    run_passes(1, 0, 2);                   // slots 0,1 (half-1 W1)
    CP_WAIT0();
    __syncthreads();
    run_passes(1, 3, 5);                   // slots 2,3 (half-1 W2)
    __syncthreads();                       // before smem reuse in epilogue

    // ---- epilogue: bias, LeakyReLU(0.2), row L2 normalize, store ----
    const int rl = lane >> 2;
    float dg2[2][2], ss2[2][2];
    #pragma unroll
    for (int mb = 0; mb < 2; ++mb)
        #pragma unroll
        for (int rh = 0; rh < 2; ++rh) {
            int grow = row0 + rg * 32 + mb * 16 + rh * 8 + rl;
            dg2[mb][rh] = (grow < Nrows) ? __ldg(deg + grow) : 0.f;
            ss2[mb][rh] = 0.f;
        }

    #pragma unroll
    for (int h = 0; h < 2; ++h)
        #pragma unroll
        for (int nb = 0; nb < 4; ++nb) {
            int col = h * 64 + cg * 32 + nb * 8 + (lane & 3) * 2;
            float2 bb1 = __ldg((const float2*)(b1v + col));
            float2 bb2 = __ldg((const float2*)(b2v + col));
            #pragma unroll
            for (int mb = 0; mb < 2; ++mb)
                #pragma unroll
                for (int rh = 0; rh < 2; ++rh) {
                    float d = dg2[mb][rh];
                    float* c = acc[h][mb][nb] + rh * 2;
                    float h0 = c[0] + (1.f + d) * bb1.x + d * bb2.x;
                    float h1 = c[1] + (1.f + d) * bb1.y + d * bb2.y;
                    h0 = (h0 > 0.f) ? h0 : 0.2f * h0;
                    h1 = (h1 > 0.f) ? h1 : 0.2f * h1;
                    c[0] = h0; c[1] = h1;
                    ss2[mb][rh] += h0 * h0 + h1 * h1;
                }
        }
    #pragma unroll
    for (int off = 1; off <= 2; off <<= 1)
        #pragma unroll
        for (int mb = 0; mb < 2; ++mb)
            #pragma unroll
            for (int rh = 0; rh < 2; ++rh)
                ss2[mb][rh] += __shfl_xor_sync(0xffffffffu, ss2[mb][rh], off);

    float* part = (float*)smem;   // [2 cg][128 rows]
    if ((lane & 3) == 0) {
        #pragma unroll
        for (int mb = 0; mb < 2; ++mb)
            #pragma unroll
            for (int rh = 0; rh < 2; ++rh)
                part[cg * 128 + rg * 32 + mb * 16 + rh * 8 + rl] = ss2[mb][rh];
    }
    __syncthreads();

    #pragma unroll
    for (int mb = 0; mb < 2; ++mb)
        #pragma unroll
        for (int rh = 0; rh < 2; ++rh) {
            int lrow128 = rg * 32 + mb * 16 + rh * 8 + rl;
            int grow = row0 + lrow128;
            float tot = ss2[mb][rh] + part[(1 ^ cg) * 128 + lrow128];
            float inv = 1.f / fmaxf(sqrtf(tot), 1e-12f);
            if (grow < Nrows) {
                #pragma unroll
                for (int h = 0; h < 2; ++h)
                    #pragma unroll
                    for (int nb = 0; nb < 4; ++nb) {
                        int col = h * 64 + cg * 32 + nb * 8 + (lane & 3) * 2;
                        float* c = acc[h][mb][nb] + rh * 2;
                        *(float2*)(outp + (size_t)grow * D + col) =
                            make_float2(c[0] * inv, c[1] * inv);
                    }
            }
        }
}

// ---------------- launch ----------------
extern "C" void kernel_launch(void* const* d_in, const int* in_sizes, int n_in,
                              void* d_out, int out_size) {
    const float* feat_user = (const float*)d_in[0];
    const float* feat_item = (const float*)d_in[1];
    const float* W1        = (const float*)d_in[2];
    const float* b1        = (const float*)d_in[3];
    const float* W2        = (const float*)d_in[4];
    const float* b2        = (const float*)d_in[5];
    const float* norm_u2i  = (const float*)d_in[6];
    const float* norm_i2u  = (const float*)d_in[7];
    const int*   e_ui_src  = (const int*)d_in[8];
    const int*   e_ui_dst  = (const int*)d_in[9];
    const int*   e_iu_src  = (const int*)d_in[10];
    const int*   e_iu_dst  = (const int*)d_in[11];
    float* out = (float*)d_out;

    const int NU = in_sizes[0] / D;
    const int NI = in_sizes[1] / D;
    const int E  = in_sizes[8];
    const int total_nodes = NU + NI;

    cudaFuncSetAttribute((const void*)gemm_mma_kernel,
                         cudaFuncAttributeMaxDynamicSharedMemorySize, SM_TOTAL);

    int init_n = total_nodes > 2 * D * D ? total_nodes : 2 * D * D;
    init_kernel<<<(init_n + 255) / 256, 256>>>(W1, W2, total_nodes);
    count_kernel<<<(2 * E + 255) / 256, 256>>>(e_ui_dst, e_iu_dst, E, NI);
    base_scan_kernel<0><<<(NI + 255) / 256, 256>>>(NI, 0);     // items
    base_scan_kernel<1><<<(NU + 255) / 256, 256>>>(NU, NI);    // users
    fill_kernel<<<(2 * E + 255) / 256, 256>>>(e_ui_src, e_ui_dst, norm_u2i,
                                              e_iu_src, e_iu_dst, norm_i2u, E, NI);
    gather_kernel<<<(total_nodes + 7) / 8, 256>>>(feat_user, feat_item, NU, NI);

    const int ublocks = (NU + 127) / 128;
    const int iblocks = (NI + 127) / 128;
    gemm_mma_kernel<<<ublocks + iblocks, 256, SM_TOTAL>>>(
        feat_user, feat_item, b1, b2, out, NU, NI, ublocks);
}

// round 16
// speedup vs baseline: 1.1338x; 1.0495x over previous
#include <cuda_runtime.h>
#include <cuda_bf16.h>
#include <cstdint>
#include <math.h>

#define D 128
#define NU_MAX 100000
#define NI_MAX 50000
#define E_MAX  500000
#define NTILE_U ((NU_MAX + 127) / 128)
#define NTILE_I ((NI_MAX + 127) / 128)

// ---------------- scratch (device globals; no allocation allowed) ----------------
__device__ float  g_deg_user[NU_MAX];
__device__ float  g_deg_item[NI_MAX];
// pre-packed, pre-swizzled A-operand tiles, one 128KB slab per output tile:
// slab = [m 0..3: Ahi, Alo, Bhi, Blo][128 rows][256B], chunk-swizzled by (row&7).
// user tiles at [0, ublocks), item tiles at [ublocks, ...). Zero-init covers tails.
__device__ unsigned char g_at[(size_t)(NTILE_U + NTILE_I) * 4 * 32768];
// pre-split, pre-swizzled bf16 weights: tiles m = {W1hi, W1lo, W2hi, W2lo}, 32KB each,
// n-halves contiguous 16KB slabs.
__device__ unsigned char g_wt[4 * 32768];
// bucket-CSR build scratch: node index space = [0,NI) items, [NI, NI+NU) users
__device__ int   g_cnt[NU_MAX + NI_MAX];
__device__ int   g_base[NU_MAX + NI_MAX];
__device__ int   g_wr[NU_MAX + NI_MAX];
__device__ int   g_cursor[2];
__device__ uint2 g_epack_u2i[E_MAX];   // (src_user, norm_bits), grouped by dst item
__device__ uint2 g_epack_i2u[E_MAX];   // (src_item, norm_bits), grouped by dst user

// ---------------- helpers ----------------
__device__ __forceinline__ uint32_t smem_u32(const void* p) {
    uint32_t a;
    asm("{ .reg .u64 t; cvta.to.shared.u64 t, %1; cvt.u32.u64 %0, t; }" : "=r"(a) : "l"(p));
    return a;
}
__device__ __forceinline__ void ldmx4(uint32_t* r, uint32_t addr) {
    asm volatile("ldmatrix.sync.aligned.m8n8.x4.shared.b16 {%0,%1,%2,%3}, [%4];"
                 : "=r"(r[0]), "=r"(r[1]), "=r"(r[2]), "=r"(r[3]) : "r"(addr));
}
__device__ __forceinline__ void mma16816(float* c, const uint32_t* a, uint32_t b0, uint32_t b1) {
    asm volatile("mma.sync.aligned.m16n8k16.row.col.f32.bf16.bf16.f32 "
                 "{%0,%1,%2,%3}, {%4,%5,%6,%7}, {%8,%9}, {%0,%1,%2,%3};"
                 : "+f"(c[0]), "+f"(c[1]), "+f"(c[2]), "+f"(c[3])
                 : "r"(a[0]), "r"(a[1]), "r"(a[2]), "r"(a[3]), "r"(b0), "r"(b1));
}
// split 4 f32 -> 4 bf16 hi (uint2) + 4 bf16 lo (uint2)
__device__ __forceinline__ void pack_hl4(const float* v, uint2* hi, uint2* lo) {
    __nv_bfloat162 h0 = __float22bfloat162_rn(make_float2(v[0], v[1]));
    __nv_bfloat162 h1 = __float22bfloat162_rn(make_float2(v[2], v[3]));
    __nv_bfloat162 l0 = __float22bfloat162_rn(
        make_float2(v[0] - __bfloat162float(h0.x), v[1] - __bfloat162float(h0.y)));
    __nv_bfloat162 l1 = __float22bfloat162_rn(
        make_float2(v[2] - __bfloat162float(h1.x), v[3] - __bfloat162float(h1.y)));
    hi->x = *(uint32_t*)&h0; hi->y = *(uint32_t*)&h1;
    lo->x = *(uint32_t*)&l0; lo->y = *(uint32_t*)&l1;
}
#define CP_ASYNC16(saddr, gptr) \
    asm volatile("cp.async.cg.shared.global [%0], [%1], 16;" :: "r"(saddr), "l"(gptr) : "memory")
#define CP_COMMIT() asm volatile("cp.async.commit_group;" ::: "memory")
#define CP_WAIT0()  asm volatile("cp.async.wait_group 0;" ::: "memory")

// ---------------- init: zero counters + weight split/swizzle (merged) ----------------
__global__ void init_kernel(const float* __restrict__ W1, const float* __restrict__ W2,
                            int total_nodes) {
    int i = blockIdx.x * blockDim.x + threadIdx.x;
    if (i < 2) g_cursor[i] = 0;
    if (i < total_nodes) g_cnt[i] = 0;
    if (i < 2 * D * D) {
        int w = i >> 14;           // 0 = W1, 1 = W2
        int k = (i >> 7) & 127;
        int n = i & 127;
        float v = __ldg((w ? W2 : W1) + k * D + n);
        __nv_bfloat16 hb = __float2bfloat16(v);
        __nv_bfloat16 lb = __float2bfloat16(v - __bfloat162float(hb));
        uint32_t off = (uint32_t)(n * 256 + (((k >> 3) ^ (n & 7)) * 16) + (k & 7) * 2);
        *(__nv_bfloat16*)(g_wt + (2 * w + 0) * 32768 + off) = hb;
        *(__nv_bfloat16*)(g_wt + (2 * w + 1) * 32768 + off) = lb;
    }
}

// ---------------- build phase ----------------
__global__ void count_kernel(const int* __restrict__ dst_u2i,
                             const int* __restrict__ dst_i2u, int E, int NI) {
    int i = blockIdx.x * blockDim.x + threadIdx.x;
    if (i < E) {
        atomicAdd(&g_cnt[__ldg(dst_u2i + i)], 1);
    } else if (i < 2 * E) {
        atomicAdd(&g_cnt[NI + __ldg(dst_i2u + (i - E))], 1);
    }
}

template <int DIR>
__global__ void base_scan_kernel(int n, int node0) {
    int i = blockIdx.x * 256 + threadIdx.x;
    int lane = threadIdx.x & 31;
    int w = threadIdx.x >> 5;
    int c = (i < n) ? g_cnt[node0 + i] : 0;
    int x = c;
    #pragma unroll
    for (int o = 1; o < 32; o <<= 1) {
        int t = __shfl_up_sync(0xffffffffu, x, o);
        if (lane >= o) x += t;
    }
    __shared__ int wsum[8];
    __shared__ int bbase;
    if (lane == 31) wsum[w] = x;
    __syncthreads();
    int wpre = 0;
    #pragma unroll
    for (int j = 0; j < 8; ++j) wpre += (j < w) ? wsum[j] : 0;
    int incl = x + wpre;
    if (threadIdx.x == 255) bbase = atomicAdd(&g_cursor[DIR], incl);
    __syncthreads();
    if (i < n) {
        int b = bbase + incl - c;
        g_base[node0 + i] = b;
        g_wr[node0 + i] = b;
    }
}

__global__ void fill_kernel(const int* __restrict__ src_u2i,
                            const int* __restrict__ dst_u2i,
                            const float* __restrict__ norm_u2i,
                            const int* __restrict__ src_i2u,
                            const int* __restrict__ dst_i2u,
                            const float* __restrict__ norm_i2u,
                            int E, int NI) {
    int i = blockIdx.x * blockDim.x + threadIdx.x;
    if (i < E) {
        int d = __ldg(dst_u2i + i);
        int p = atomicAdd(&g_wr[d], 1);
        if (p < E_MAX)
            g_epack_u2i[p] = make_uint2((uint32_t)__ldg(src_u2i + i),
                                        __float_as_uint(__ldg(norm_u2i + i)));
    } else if (i < 2 * E) {
        int j = i - E;
        int d = __ldg(dst_i2u + j);
        int p = atomicAdd(&g_wr[NI + d], 1);
        if (p < E_MAX)
            g_epack_i2u[p] = make_uint2((uint32_t)__ldg(src_i2u + j),
                                        __float_as_uint(__ldg(norm_i2u + j)));
    }
}

// ---------------- gather + pack: one warp per dst node ----------------
// Accumulates agg in registers, then fuses the gemm's A-operand prep:
// A = feat+agg, B = feat*agg, bf16 hi/lo split, written pre-swizzled to g_at.
__global__ void gather_kernel(const float* __restrict__ feat_user,
                              const float* __restrict__ feat_item,
                              int NU, int NI, int ublocks) {
    int gw = (blockIdx.x * blockDim.x + threadIdx.x) >> 5;
    int lane = threadIdx.x & 31;
    int total = NI + NU;
    if (gw >= total) return;

    const bool is_item = gw < NI;
    const int node = is_item ? gw : gw - NI;
    const float* fs = is_item ? feat_user : feat_item;   // source-side features
    const float* fd = is_item ? feat_item : feat_user;   // dst node's own features
    const uint2* ep = is_item ? g_epack_u2i : g_epack_i2u;
    float* degp = is_item ? (g_deg_item + node) : (g_deg_user + node);
    const int tile_idx = is_item ? (ublocks + (node >> 7)) : (node >> 7);

    int e  = __ldg(g_base + gw);
    int e1 = e + __ldg(g_cnt + gw);

    float4 acc = make_float4(0.f, 0.f, 0.f, 0.f);
    float dg = 0.f;
    uint2 pk;
    float4 f;
    if (e < e1) {
        pk = __ldg(ep + e);
        f = __ldg(((const float4*)(fs + (size_t)pk.x * D)) + lane);
    }
    while (e < e1) {
        float w = __uint_as_float(pk.y);
        float4 cf = f;
        ++e;
        if (e < e1) {
            pk = __ldg(ep + e);
            f = __ldg(((const float4*)(fs + (size_t)pk.x * D)) + lane);
        }
        acc.x += w * cf.x;
        acc.y += w * cf.y;
        acc.z += w * cf.z;
        acc.w += w * cf.w;
        dg += w;
    }

    // fused A-operand pack (identical math to the old gemm prologue)
    float4 fo = __ldg(((const float4*)(fd + (size_t)node * D)) + lane);
    float Av[4] = {fo.x + acc.x, fo.y + acc.y, fo.z + acc.z, fo.w + acc.w};
    float Bv[4] = {fo.x * acc.x, fo.y * acc.y, fo.z * acc.z, fo.w * acc.w};
    uint2 ahi, alo, bhi, blo;
    pack_hl4(Av, &ahi, &alo);
    pack_hl4(Bv, &bhi, &blo);
    int row = node & 127;
    uint32_t off = (uint32_t)(row * 256 + (((lane >> 1) ^ (row & 7)) * 16) + (lane & 1) * 8);
    unsigned char* slab = g_at + (size_t)tile_idx * 4 * 32768 + off;
    *(uint2*)(slab + 0 * 32768) = ahi;
    *(uint2*)(slab + 1 * 32768) = alo;
    *(uint2*)(slab + 2 * 32768) = bhi;
    *(uint2*)(slab + 3 * 32768) = blo;
    if (lane == 0) *degp = dg;
}

// ---------------- mma.sync fused dual-GEMM + bias + LeakyReLU + row L2-normalize ----------------
// 256 threads / 8 warps, warp tile 32 rows x 16 cols (proven R13/R15 shape).
// Prologue is now pure cp.async: A slab 128KB + W half-0 64KB.
#define SM_W_OFF 131072
#define SM_TOTAL (131072 + 65536)

__global__ __launch_bounds__(256, 1)
void gemm_mma_kernel(const float* __restrict__ b1v,
                     const float* __restrict__ b2v,
                     float* __restrict__ out,
                     int NU, int NI, int ublocks) {
    extern __shared__ char smem[];
    const uint32_t sbase = smem_u32(smem);
    const int tid = threadIdx.x;
    const int wid = tid >> 5;
    const int lane = tid & 31;

    const bool is_user = (int)blockIdx.x < ublocks;
    const int bx = is_user ? blockIdx.x : blockIdx.x - ublocks;
    const int Nrows = is_user ? NU : NI;
    const int row0 = bx * 128;
    const float* deg = is_user ? g_deg_user : g_deg_item;
    float* outp = is_user ? out : out + (size_t)NU * D;
    const int tile_idx = (int)blockIdx.x;   // user tiles [0,ublocks), items after

    // ---- cp.async prologue: A slab (4 x 32KB) + W half-0 (4 x 16KB) ----
    const unsigned char* aslab = g_at + (size_t)tile_idx * 4 * 32768;
    #pragma unroll
    for (int m = 0; m < 4; ++m)
        for (int t = tid; t < 2048; t += 256)
            CP_ASYNC16(sbase + m * 32768 + t * 16, (const void*)(aslab + m * 32768 + t * 16));
    #pragma unroll
    for (int m = 0; m < 4; ++m)
        for (int t = tid; t < 1024; t += 256)
            CP_ASYNC16(sbase + SM_W_OFF + m * 16384 + t * 16,
                       (const void*)(g_wt + m * 32768 + t * 16));
    CP_COMMIT();
    CP_WAIT0();
    __syncthreads();

    const int rg = wid & 3;      // 4 row groups of 32 rows
    const int cg = wid >> 2;     // 2 col groups of 32 cols (within current 64-col half)
    const int lrow = lane & 15;
    const int lkh = lane >> 4;
    const int lswz = lrow & 7;

    float acc[2][2][4][4];       // [h][mb][nb][c]
    #pragma unroll
    for (int h = 0; h < 2; ++h)
        #pragma unroll
        for (int mb = 0; mb < 2; ++mb)
            #pragma unroll
            for (int nb = 0; nb < 4; ++nb)
                #pragma unroll
                for (int e = 0; e < 4; ++e) acc[h][mb][nb][e] = 0.f;

    const int aidx[6] = {0, 0, 1, 2, 2, 3};   // Ahi Ahi Alo Bhi Bhi Blo
    const int widx[6] = {0, 1, 0, 2, 3, 2};   // W1hi W1lo W1hi W2hi W2lo W2hi

    const uint32_t rowA0 = (uint32_t)((rg * 32 + lrow) * 256);
    const uint32_t rowA1 = rowA0 + 16 * 256;
    const uint32_t rowB0 = (uint32_t)((cg * 32 + lrow) * 256);
    const uint32_t rowB1 = rowB0 + 16 * 256;

    auto run_passes = [&](int h, int p0, int p1) {
        for (int p = p0; p <= p1; ++p) {
            const uint32_t abase = sbase + (uint32_t)(aidx[p] * 32768);
            const uint32_t wbase = sbase + SM_W_OFF + (uint32_t)(widx[p] * 16384);
            #pragma unroll
            for (int ks = 0; ks < 8; ++ks) {
                uint32_t coff = (uint32_t)(((ks * 2 + lkh) ^ lswz) * 16);
                uint32_t a0r[4], a1r[4], b0r[4], b1r[4];
                ldmx4(a0r, abase + rowA0 + coff);
                ldmx4(a1r, abase + rowA1 + coff);
                ldmx4(b0r, wbase + rowB0 + coff);
                ldmx4(b1r, wbase + rowB1 + coff);
                #pragma unroll
                for (int mb = 0; mb < 2; ++mb) {
                    const uint32_t* a = mb ? a1r : a0r;
                    mma16816(acc[h][mb][0], a, b0r[0], b0r[2]);
                    mma16816(acc[h][mb][1], a, b0r[1], b0r[3]);
                    mma16816(acc[h][mb][2], a, b1r[0], b1r[2]);
                    mma16816(acc[h][mb][3], a, b1r[1], b1r[3]);
                }
            }
        }
    };

    // half 0, W1 passes (W slots 0,1)
    run_passes(0, 0, 2);
    __syncthreads();                       // all warps done with slots 0,1
    #pragma unroll
    for (int m = 0; m < 2; ++m)
        for (int t = tid; t < 1024; t += 256)
            CP_ASYNC16(sbase + SM_W_OFF + m * 16384 + t * 16,
                       (const void*)(g_wt + m * 32768 + 16384 + t * 16));
    CP_COMMIT();
    run_passes(0, 3, 5);                   // uses slots 2,3
    CP_WAIT0();
    __syncthreads();                       // W1' landed; all warps done with slots 2,3
    #pragma unroll
    for (int m = 2; m < 4; ++m)
        for (int t = tid; t < 1024; t += 256)
            CP_ASYNC16(sbase + SM_W_OFF + m * 16384 + t * 16,
                       (const void*)(g_wt + m * 32768 + 16384 + t * 16));
    CP_COMMIT();
    run_passes(1, 0, 2);                   // slots 0,1 (half-1 W1)
    CP_WAIT0();
    __syncthreads();
    run_passes(1, 3, 5);                   // slots 2,3 (half-1 W2)
    __syncthreads();                       // before smem reuse in epilogue

    // ---- epilogue: bias, LeakyReLU(0.2), row L2 normalize, store ----
    const int rl = lane >> 2;
    float dg2[2][2], ss2[2][2];
    #pragma unroll
    for (int mb = 0; mb < 2; ++mb)
        #pragma unroll
        for (int rh = 0; rh < 2; ++rh) {
            int grow = row0 + rg * 32 + mb * 16 + rh * 8 + rl;
            dg2[mb][rh] = (grow < Nrows) ? __ldg(deg + grow) : 0.f;
            ss2[mb][rh] = 0.f;
        }

    #pragma unroll
    for (int h = 0; h < 2; ++h)
        #pragma unroll
        for (int nb = 0; nb < 4; ++nb) {
            int col = h * 64 + cg * 32 + nb * 8 + (lane & 3) * 2;
            float2 bb1 = __ldg((const float2*)(b1v + col));
            float2 bb2 = __ldg((const float2*)(b2v + col));
            #pragma unroll
            for (int mb = 0; mb < 2; ++mb)
                #pragma unroll
                for (int rh = 0; rh < 2; ++rh) {
                    float d = dg2[mb][rh];
                    float* c = acc[h][mb][nb] + rh * 2;
                    float h0 = c[0] + (1.f + d) * bb1.x + d * bb2.x;
                    float h1 = c[1] + (1.f + d) * bb1.y + d * bb2.y;
                    h0 = (h0 > 0.f) ? h0 : 0.2f * h0;
                    h1 = (h1 > 0.f) ? h1 : 0.2f * h1;
                    c[0] = h0; c[1] = h1;
                    ss2[mb][rh] += h0 * h0 + h1 * h1;
                }
        }
    #pragma unroll
    for (int off = 1; off <= 2; off <<= 1)
        #pragma unroll
        for (int mb = 0; mb < 2; ++mb)
            #pragma unroll
            for (int rh = 0; rh < 2; ++rh)
                ss2[mb][rh] += __shfl_xor_sync(0xffffffffu, ss2[mb][rh], off);

    float* part = (float*)smem;   // [2 cg][128 rows]
    if ((lane & 3) == 0) {
        #pragma unroll
        for (int mb = 0; mb < 2; ++mb)
            #pragma unroll
            for (int rh = 0; rh < 2; ++rh)
                part[cg * 128 + rg * 32 + mb * 16 + rh * 8 + rl] = ss2[mb][rh];
    }
    __syncthreads();

    #pragma unroll
    for (int mb = 0; mb < 2; ++mb)
        #pragma unroll
        for (int rh = 0; rh < 2; ++rh) {
            int lrow128 = rg * 32 + mb * 16 + rh * 8 + rl;
            int grow = row0 + lrow128;
            float tot = ss2[mb][rh] + part[(1 ^ cg) * 128 + lrow128];
            float inv = 1.f / fmaxf(sqrtf(tot), 1e-12f);
            if (grow < Nrows) {
                #pragma unroll
                for (int h = 0; h < 2; ++h)
                    #pragma unroll
                    for (int nb = 0; nb < 4; ++nb) {
                        int col = h * 64 + cg * 32 + nb * 8 + (lane & 3) * 2;
                        float* c = acc[h][mb][nb] + rh * 2;
                        *(float2*)(outp + (size_t)grow * D + col) =
                            make_float2(c[0] * inv, c[1] * inv);
                    }
            }
        }
}

// ---------------- launch ----------------
extern "C" void kernel_launch(void* const* d_in, const int* in_sizes, int n_in,
                              void* d_out, int out_size) {
    const float* feat_user = (const float*)d_in[0];
    const float* feat_item = (const float*)d_in[1];
    const float* W1        = (const float*)d_in[2];
    const float* b1        = (const float*)d_in[3];
    const float* W2        = (const float*)d_in[4];
    const float* b2        = (const float*)d_in[5];
    const float* norm_u2i  = (const float*)d_in[6];
    const float* norm_i2u  = (const float*)d_in[7];
    const int*   e_ui_src  = (const int*)d_in[8];
    const int*   e_ui_dst  = (const int*)d_in[9];
    const int*   e_iu_src  = (const int*)d_in[10];
    const int*   e_iu_dst  = (const int*)d_in[11];
    float* out = (float*)d_out;

    const int NU = in_sizes[0] / D;
    const int NI = in_sizes[1] / D;
    const int E  = in_sizes[8];
    const int total_nodes = NU + NI;

    cudaFuncSetAttribute((const void*)gemm_mma_kernel,
                         cudaFuncAttributeMaxDynamicSharedMemorySize, SM_TOTAL);

    const int ublocks = (NU + 127) / 128;
    const int iblocks = (NI + 127) / 128;

    int init_n = total_nodes > 2 * D * D ? total_nodes : 2 * D * D;
    init_kernel<<<(init_n + 255) / 256, 256>>>(W1, W2, total_nodes);
    count_kernel<<<(2 * E + 255) / 256, 256>>>(e_ui_dst, e_iu_dst, E, NI);
    base_scan_kernel<0><<<(NI + 255) / 256, 256>>>(NI, 0);     // items
    base_scan_kernel<1><<<(NU + 255) / 256, 256>>>(NU, NI);    // users
    fill_kernel<<<(2 * E + 255) / 256, 256>>>(e_ui_src, e_ui_dst, norm_u2i,
                                              e_iu_src, e_iu_dst, norm_i2u, E, NI);
    gather_kernel<<<(total_nodes + 7) / 8, 256>>>(feat_user, feat_item, NU, NI, ublocks);

    gemm_mma_kernel<<<ublocks + iblocks, 256, SM_TOTAL>>>(b1, b2, out, NU, NI, ublocks);
}

// round 17
// speedup vs baseline: 1.2048x; 1.0626x over previous
#include <cuda_runtime.h>
#include <cuda_bf16.h>
#include <cstdint>
#include <math.h>

#define D 128
#define NU_MAX 100000
#define NI_MAX 50000
#define E_MAX  500000
#define NTILE_U ((NU_MAX + 127) / 128)
#define NTILE_I ((NI_MAX + 127) / 128)

// ---------------- scratch (device globals; no allocation allowed) ----------------
__device__ float  g_deg_user[NU_MAX];
__device__ float  g_deg_item[NI_MAX];
// pre-packed, pre-swizzled A-operand tiles, one 128KB slab per output tile:
// slab = [m 0..3: Ahi, Alo, Bhi, Blo][128 rows][256B], chunk-swizzled by (row&7).
__device__ unsigned char g_at[(size_t)(NTILE_U + NTILE_I) * 4 * 32768];
// pre-split, pre-swizzled bf16 weights: tiles m = {W1hi, W1lo, W2hi, W2lo}, 32KB each,
// n-halves contiguous 16KB slabs.
__device__ unsigned char g_wt[4 * 32768];
// bucket-CSR build scratch: node index space = [0,NI) items, [NI, NI+NU) users
__device__ int   g_cnt[NU_MAX + NI_MAX];
__device__ int   g_base[NU_MAX + NI_MAX];
__device__ int   g_wr[NU_MAX + NI_MAX];
__device__ int   g_cursor[2];
__device__ uint2 g_epack_u2i[E_MAX];   // (src_user, norm_bits), grouped by dst item
__device__ uint2 g_epack_i2u[E_MAX];   // (src_item, norm_bits), grouped by dst user

// ---------------- helpers ----------------
__device__ __forceinline__ uint32_t smem_u32(const void* p) {
    uint32_t a;
    asm("{ .reg .u64 t; cvta.to.shared.u64 t, %1; cvt.u32.u64 %0, t; }" : "=r"(a) : "l"(p));
    return a;
}
__device__ __forceinline__ void ldmx4(uint32_t* r, uint32_t addr) {
    asm volatile("ldmatrix.sync.aligned.m8n8.x4.shared.b16 {%0,%1,%2,%3}, [%4];"
                 : "=r"(r[0]), "=r"(r[1]), "=r"(r[2]), "=r"(r[3]) : "r"(addr));
}
__device__ __forceinline__ void mma16816(float* c, const uint32_t* a, uint32_t b0, uint32_t b1) {
    asm volatile("mma.sync.aligned.m16n8k16.row.col.f32.bf16.bf16.f32 "
                 "{%0,%1,%2,%3}, {%4,%5,%6,%7}, {%8,%9}, {%0,%1,%2,%3};"
                 : "+f"(c[0]), "+f"(c[1]), "+f"(c[2]), "+f"(c[3])
                 : "r"(a[0]), "r"(a[1]), "r"(a[2]), "r"(a[3]), "r"(b0), "r"(b1));
}
__device__ __forceinline__ void pack_hl4(const float* v, uint2* hi, uint2* lo) {
    __nv_bfloat162 h0 = __float22bfloat162_rn(make_float2(v[0], v[1]));
    __nv_bfloat162 h1 = __float22bfloat162_rn(make_float2(v[2], v[3]));
    __nv_bfloat162 l0 = __float22bfloat162_rn(
        make_float2(v[0] - __bfloat162float(h0.x), v[1] - __bfloat162float(h0.y)));
    __nv_bfloat162 l1 = __float22bfloat162_rn(
        make_float2(v[2] - __bfloat162float(h1.x), v[3] - __bfloat162float(h1.y)));
    hi->x = *(uint32_t*)&h0; hi->y = *(uint32_t*)&h1;
    lo->x = *(uint32_t*)&l0; lo->y = *(uint32_t*)&l1;
}
#define CP_ASYNC16(saddr, gptr) \
    asm volatile("cp.async.cg.shared.global [%0], [%1], 16;" :: "r"(saddr), "l"(gptr) : "memory")
#define CP_COMMIT() asm volatile("cp.async.commit_group;" ::: "memory")

// ---------------- init: zero counters + weight split/swizzle (merged) ----------------
__global__ void init_kernel(const float* __restrict__ W1, const float* __restrict__ W2,
                            int total_nodes) {
    int i = blockIdx.x * blockDim.x + threadIdx.x;
    if (i < 2) g_cursor[i] = 0;
    if (i < total_nodes) g_cnt[i] = 0;
    if (i < 2 * D * D) {
        int w = i >> 14;           // 0 = W1, 1 = W2
        int k = (i >> 7) & 127;
        int n = i & 127;
        float v = __ldg((w ? W2 : W1) + k * D + n);
        __nv_bfloat16 hb = __float2bfloat16(v);
        __nv_bfloat16 lb = __float2bfloat16(v - __bfloat162float(hb));
        uint32_t off = (uint32_t)(n * 256 + (((k >> 3) ^ (n & 7)) * 16) + (k & 7) * 2);
        *(__nv_bfloat16*)(g_wt + (2 * w + 0) * 32768 + off) = hb;
        *(__nv_bfloat16*)(g_wt + (2 * w + 1) * 32768 + off) = lb;
    }
}

// ---------------- build phase ----------------
__global__ void count_kernel(const int* __restrict__ dst_u2i,
                             const int* __restrict__ dst_i2u, int E, int NI) {
    int i = blockIdx.x * blockDim.x + threadIdx.x;
    if (i < E) {
        atomicAdd(&g_cnt[__ldg(dst_u2i + i)], 1);
    } else if (i < 2 * E) {
        atomicAdd(&g_cnt[NI + __ldg(dst_i2u + (i - E))], 1);
    }
}

// Exclusive-offset assignment for both node ranges in ONE launch:
// blocks [0, iblk) cover items (dir 0), the rest cover users (dir 1).
__global__ void base_scan_all(int NI, int NU, int iblk) {
    const bool item = (int)blockIdx.x < iblk;
    const int dir = item ? 0 : 1;
    const int n = item ? NI : NU;
    const int node0 = item ? 0 : NI;
    const int bx = item ? blockIdx.x : blockIdx.x - iblk;
    int i = bx * 256 + threadIdx.x;
    int lane = threadIdx.x & 31;
    int w = threadIdx.x >> 5;
    int c = (i < n) ? g_cnt[node0 + i] : 0;
    int x = c;
    #pragma unroll
    for (int o = 1; o < 32; o <<= 1) {
        int t = __shfl_up_sync(0xffffffffu, x, o);
        if (lane >= o) x += t;
    }
    __shared__ int wsum[8];
    __shared__ int bbase;
    if (lane == 31) wsum[w] = x;
    __syncthreads();
    int wpre = 0;
    #pragma unroll
    for (int j = 0; j < 8; ++j) wpre += (j < w) ? wsum[j] : 0;
    int incl = x + wpre;
    if (threadIdx.x == 255) bbase = atomicAdd(&g_cursor[dir], incl);
    __syncthreads();
    if (i < n) {
        int b = bbase + incl - c;
        g_base[node0 + i] = b;
        g_wr[node0 + i] = b;
    }
}

__global__ void fill_kernel(const int* __restrict__ src_u2i,
                            const int* __restrict__ dst_u2i,
                            const float* __restrict__ norm_u2i,
                            const int* __restrict__ src_i2u,
                            const int* __restrict__ dst_i2u,
                            const float* __restrict__ norm_i2u,
                            int E, int NI) {
    int i = blockIdx.x * blockDim.x + threadIdx.x;
    if (i < E) {
        int d = __ldg(dst_u2i + i);
        int p = atomicAdd(&g_wr[d], 1);
        if (p < E_MAX)
            g_epack_u2i[p] = make_uint2((uint32_t)__ldg(src_u2i + i),
                                        __float_as_uint(__ldg(norm_u2i + i)));
    } else if (i < 2 * E) {
        int j = i - E;
        int d = __ldg(dst_i2u + j);
        int p = atomicAdd(&g_wr[NI + d], 1);
        if (p < E_MAX)
            g_epack_i2u[p] = make_uint2((uint32_t)__ldg(src_i2u + j),
                                        __float_as_uint(__ldg(norm_i2u + j)));
    }
}

// ---------------- gather + pack: one warp per dst node ----------------
__global__ void gather_kernel(const float* __restrict__ feat_user,
                              const float* __restrict__ feat_item,
                              int NU, int NI, int ublocks) {
    int gw = (blockIdx.x * blockDim.x + threadIdx.x) >> 5;
    int lane = threadIdx.x & 31;
    int total = NI + NU;
    if (gw >= total) return;

    const bool is_item = gw < NI;
    const int node = is_item ? gw : gw - NI;
    const float* fs = is_item ? feat_user : feat_item;
    const float* fd = is_item ? feat_item : feat_user;
    const uint2* ep = is_item ? g_epack_u2i : g_epack_i2u;
    float* degp = is_item ? (g_deg_item + node) : (g_deg_user + node);
    const int tile_idx = is_item ? (ublocks + (node >> 7)) : (node >> 7);

    int e  = __ldg(g_base + gw);
    int e1 = e + __ldg(g_cnt + gw);

    float4 acc = make_float4(0.f, 0.f, 0.f, 0.f);
    float dg = 0.f;
    uint2 pk;
    float4 f;
    if (e < e1) {
        pk = __ldg(ep + e);
        f = __ldg(((const float4*)(fs + (size_t)pk.x * D)) + lane);
    }
    while (e < e1) {
        float w = __uint_as_float(pk.y);
        float4 cf = f;
        ++e;
        if (e < e1) {
            pk = __ldg(ep + e);
            f = __ldg(((const float4*)(fs + (size_t)pk.x * D)) + lane);
        }
        acc.x += w * cf.x;
        acc.y += w * cf.y;
        acc.z += w * cf.z;
        acc.w += w * cf.w;
        dg += w;
    }

    float4 fo = __ldg(((const float4*)(fd + (size_t)node * D)) + lane);
    float Av[4] = {fo.x + acc.x, fo.y + acc.y, fo.z + acc.z, fo.w + acc.w};
    float Bv[4] = {fo.x * acc.x, fo.y * acc.y, fo.z * acc.z, fo.w * acc.w};
    uint2 ahi, alo, bhi, blo;
    pack_hl4(Av, &ahi, &alo);
    pack_hl4(Bv, &bhi, &blo);
    int row = node & 127;
    uint32_t off = (uint32_t)(row * 256 + (((lane >> 1) ^ (row & 7)) * 16) + (lane & 1) * 8);
    unsigned char* slab = g_at + (size_t)tile_idx * 4 * 32768 + off;
    *(uint2*)(slab + 0 * 32768) = ahi;
    *(uint2*)(slab + 1 * 32768) = alo;
    *(uint2*)(slab + 2 * 32768) = bhi;
    *(uint2*)(slab + 3 * 32768) = blo;
    if (lane == 0) *degp = dg;
}

// ---------------- mma.sync fused dual-GEMM + bias + LeakyReLU + row L2-normalize ----------------
// 256 threads / 8 warps, warp tile 32 rows x 16 cols. A-chunk-major pass schedule with
// graduated cp.async waits: only W1+Ahi (64KB) exposed; Alo/Bhi/Blo/W2 stream behind compute.
// smem: A chunks 4x32KB at 0, W slots: WA(32K) WB(32K) WC(32K) at 128KB. Total 224KB.
#define SM_WA 131072
#define SM_WB (131072 + 32768)
#define SM_WC (131072 + 65536)
#define SM_TOTAL (131072 + 98304)

__global__ __launch_bounds__(256, 1)
void gemm_mma_kernel(const float* __restrict__ b1v,
                     const float* __restrict__ b2v,
                     float* __restrict__ out,
                     int NU, int NI, int ublocks) {
    extern __shared__ char smem[];
    const uint32_t sbase = smem_u32(smem);
    const int tid = threadIdx.x;
    const int wid = tid >> 5;
    const int lane = tid & 31;

    const bool is_user = (int)blockIdx.x < ublocks;
    const int bx = is_user ? blockIdx.x : blockIdx.x - ublocks;
    const int Nrows = is_user ? NU : NI;
    const int row0 = bx * 128;
    const float* deg = is_user ? g_deg_user : g_deg_item;
    float* outp = is_user ? out : out + (size_t)NU * D;
    const unsigned char* aslab = g_at + (size_t)blockIdx.x * 4 * 32768;

    // ---- issue all cp.async groups up front ----
    // c0: WA<-W1hi, WB<-W1lo ; c1..c4: A0..A3 ; c5: WC<-W2hi
    for (int t = tid; t < 2048; t += 256)
        CP_ASYNC16(sbase + SM_WA + t * 16, (const void*)(g_wt + t * 16));
    for (int t = tid; t < 2048; t += 256)
        CP_ASYNC16(sbase + SM_WB + t * 16, (const void*)(g_wt + 32768 + t * 16));
    CP_COMMIT();
    #pragma unroll
    for (int m = 0; m < 4; ++m) {
        for (int t = tid; t < 2048; t += 256)
            CP_ASYNC16(sbase + m * 32768 + t * 16, (const void*)(aslab + m * 32768 + t * 16));
        CP_COMMIT();
    }
    for (int t = tid; t < 2048; t += 256)
        CP_ASYNC16(sbase + SM_WC + t * 16, (const void*)(g_wt + 65536 + t * 16));
    CP_COMMIT();

    const int rg = wid & 3;      // 4 row groups of 32 rows
    const int cg = wid >> 2;     // 2 col groups of 32 cols (within current 64-col half)
    const int lrow = lane & 15;
    const int lkh = lane >> 4;
    const int lswz = lrow & 7;

    float acc[2][2][4][4];       // [h][mb][nb][c]
    #pragma unroll
    for (int h = 0; h < 2; ++h)
        #pragma unroll
        for (int mb = 0; mb < 2; ++mb)
            #pragma unroll
            for (int nb = 0; nb < 4; ++nb)
                #pragma unroll
                for (int e = 0; e < 4; ++e) acc[h][mb][nb][e] = 0.f;

    const uint32_t rowA0 = (uint32_t)((rg * 32 + lrow) * 256);
    const uint32_t rowA1 = rowA0 + 16 * 256;
    const uint32_t rowB0 = (uint32_t)((cg * 32 + lrow) * 256);
    const uint32_t rowB1 = rowB0 + 16 * 256;

    // one pass-unit: A chunk at aoff, W half-slab at woff(+h*16KB), accumulate into acc[h]
    auto pass = [&](uint32_t aoff, uint32_t woff, int h) {
        const uint32_t abase = sbase + aoff;
        const uint32_t wbase = sbase + woff + (uint32_t)(h * 16384);
        #pragma unroll
        for (int ks = 0; ks < 8; ++ks) {
            uint32_t coff = (uint32_t)(((ks * 2 + lkh) ^ lswz) * 16);
            uint32_t a0r[4], a1r[4], b0r[4], b1r[4];
            ldmx4(a0r, abase + rowA0 + coff);
            ldmx4(a1r, abase + rowA1 + coff);
            ldmx4(b0r, wbase + rowB0 + coff);
            ldmx4(b1r, wbase + rowB1 + coff);
            #pragma unroll
            for (int mb = 0; mb < 2; ++mb) {
                const uint32_t* a = mb ? a1r : a0r;
                mma16816(acc[h][mb][0], a, b0r[0], b0r[2]);
                mma16816(acc[h][mb][1], a, b0r[1], b0r[3]);
                mma16816(acc[h][mb][2], a, b1r[0], b1r[2]);
                mma16816(acc[h][mb][3], a, b1r[1], b1r[3]);
            }
        }
    };

    // Ahi chunk: needs c0 (W1) + c1 (A0)  -> pending <= 4
    asm volatile("cp.async.wait_group 4;" ::: "memory");
    __syncthreads();
    pass(0, SM_WA, 0); pass(0, SM_WA, 1);     // Ahi x W1hi
    pass(0, SM_WB, 0); pass(0, SM_WB, 1);     // Ahi x W1lo
    // Alo chunk: needs c2 -> pending <= 3
    asm volatile("cp.async.wait_group 3;" ::: "memory");
    __syncthreads();
    pass(32768, SM_WA, 0); pass(32768, SM_WA, 1);   // Alo x W1hi
    __syncthreads();                                 // all warps done with WB (W1lo)
    // c6: WB <- W2lo
    for (int t = tid; t < 2048; t += 256)
        CP_ASYNC16(sbase + SM_WB + t * 16, (const void*)(g_wt + 98304 + t * 16));
    CP_COMMIT();
    // Bhi x W2hi: needs c3 (A2) + c5 (WC) -> pending <= 1 (c6)
    asm volatile("cp.async.wait_group 1;" ::: "memory");
    __syncthreads();
    pass(65536, SM_WC, 0); pass(65536, SM_WC, 1);   // Bhi x W2hi
    // Bhi x W2lo: needs c6 -> pending 0
    asm volatile("cp.async.wait_group 0;" ::: "memory");
    __syncthreads();
    pass(65536, SM_WB, 0); pass(65536, SM_WB, 1);   // Bhi x W2lo
    pass(98304, SM_WC, 0); pass(98304, SM_WC, 1);   // Blo x W2hi
    __syncthreads();                                 // before smem reuse in epilogue

    // ---- epilogue: bias, LeakyReLU(0.2), row L2 normalize, store ----
    const int rl = lane >> 2;
    float dg2[2][2], ss2[2][2];
    #pragma unroll
    for (int mb = 0; mb < 2; ++mb)
        #pragma unroll
        for (int rh = 0; rh < 2; ++rh) {
            int grow = row0 + rg * 32 + mb * 16 + rh * 8 + rl;
            dg2[mb][rh] = (grow < Nrows) ? __ldg(deg + grow) : 0.f;
            ss2[mb][rh] = 0.f;
        }

    #pragma unroll
    for (int h = 0; h < 2; ++h)
        #pragma unroll
        for (int nb = 0; nb < 4; ++nb) {
            int col = h * 64 + cg * 32 + nb * 8 + (lane & 3) * 2;
            float2 bb1 = __ldg((const float2*)(b1v + col));
            float2 bb2 = __ldg((const float2*)(b2v + col));
            #pragma unroll
            for (int mb = 0; mb < 2; ++mb)
                #pragma unroll
                for (int rh = 0; rh < 2; ++rh) {
                    float d = dg2[mb][rh];
                    float* c = acc[h][mb][nb] + rh * 2;
                    float h0 = c[0] + (1.f + d) * bb1.x + d * bb2.x;
                    float h1 = c[1] + (1.f + d) * bb1.y + d * bb2.y;
                    h0 = (h0 > 0.f) ? h0 : 0.2f * h0;
                    h1 = (h1 > 0.f) ? h1 : 0.2f * h1;
                    c[0] = h0; c[1] = h1;
                    ss2[mb][rh] += h0 * h0 + h1 * h1;
                }
        }
    #pragma unroll
    for (int off = 1; off <= 2; off <<= 1)
        #pragma unroll
        for (int mb = 0; mb < 2; ++mb)
            #pragma unroll
            for (int rh = 0; rh < 2; ++rh)
                ss2[mb][rh] += __shfl_xor_sync(0xffffffffu, ss2[mb][rh], off);

    float* part = (float*)smem;   // reuse A region: [2 cg][128 rows]
    if ((lane & 3) == 0) {
        #pragma unroll
        for (int mb = 0; mb < 2; ++mb)
            #pragma unroll
            for (int rh = 0; rh < 2; ++rh)
                part[cg * 128 + rg * 32 + mb * 16 + rh * 8 + rl] = ss2[mb][rh];
    }
    __syncthreads();

    #pragma unroll
    for (int mb = 0; mb < 2; ++mb)
        #pragma unroll
        for (int rh = 0; rh < 2; ++rh) {
            int lrow128 = rg * 32 + mb * 16 + rh * 8 + rl;
            int grow = row0 + lrow128;
            float tot = ss2[mb][rh] + part[(1 ^ cg) * 128 + lrow128];
            float inv = 1.f / fmaxf(sqrtf(tot), 1e-12f);
            if (grow < Nrows) {
                #pragma unroll
                for (int h = 0; h < 2; ++h)
                    #pragma unroll
                    for (int nb = 0; nb < 4; ++nb) {
                        int col = h * 64 + cg * 32 + nb * 8 + (lane & 3) * 2;
                        float* c = acc[h][mb][nb] + rh * 2;
                        *(float2*)(outp + (size_t)grow * D + col) =
                            make_float2(c[0] * inv, c[1] * inv);
                    }
            }
        }
}

// ---------------- launch ----------------
extern "C" void kernel_launch(void* const* d_in, const int* in_sizes, int n_in,
                              void* d_out, int out_size) {
    const float* feat_user = (const float*)d_in[0];
    const float* feat_item = (const float*)d_in[1];
    const float* W1        = (const float*)d_in[2];
    const float* b1        = (const float*)d_in[3];
    const float* W2        = (const float*)d_in[4];
    const float* b2        = (const float*)d_in[5];
    const float* norm_u2i  = (const float*)d_in[6];
    const float* norm_i2u  = (const float*)d_in[7];
    const int*   e_ui_src  = (const int*)d_in[8];
    const int*   e_ui_dst  = (const int*)d_in[9];
    const int*   e_iu_src  = (const int*)d_in[10];
    const int*   e_iu_dst  = (const int*)d_in[11];
    float* out = (float*)d_out;

    const int NU = in_sizes[0] / D;
    const int NI = in_sizes[1] / D;
    const int E  = in_sizes[8];
    const int total_nodes = NU + NI;

    cudaFuncSetAttribute((const void*)gemm_mma_kernel,
                         cudaFuncAttributeMaxDynamicSharedMemorySize, SM_TOTAL);

    const int ublocks = (NU + 127) / 128;
    const int iblocks = (NI + 127) / 128;

    int init_n = total_nodes > 2 * D * D ? total_nodes : 2 * D * D;
    init_kernel<<<(init_n + 255) / 256, 256>>>(W1, W2, total_nodes);
    count_kernel<<<(2 * E + 255) / 256, 256>>>(e_ui_dst, e_iu_dst, E, NI);
    {
        int iblk = (NI + 255) / 256;
        int ublk = (NU + 255) / 256;
        base_scan_all<<<iblk + ublk, 256>>>(NI, NU, iblk);
    }
    fill_kernel<<<(2 * E + 255) / 256, 256>>>(e_ui_src, e_ui_dst, norm_u2i,
                                              e_iu_src, e_iu_dst, norm_i2u, E, NI);
    gather_kernel<<<(total_nodes + 7) / 8, 256>>>(feat_user, feat_item, NU, NI, ublocks);

    gemm_mma_kernel<<<ublocks + iblocks, 256, SM_TOTAL>>>(b1, b2, out, NU, NI, ublocks);
}